// round 11
// baseline (speedup 1.0000x reference)
#include <cuda_runtime.h>
#include <cuda_bf16.h>
#include <cstdint>

#define BATCH 4
#define CIN   128
#define COUT  256
#define HW    1024
#define TILE_O 32
#define TILE_P 64
#define THREADS 128

// smem (bytes): strides are 16B multiples with (stride/4 mod 32)==4 -> ldmatrix
// row addresses walk 4 banks per row, conflict-free per 8-row phase.
#define A_STRIDE 272            // 128 halves + 8 pad
#define B_STRIDE 144            // 64 halves + 8 pad
#define SMEM_AH  0                                 // bf16(0.5*w)
#define SMEM_AA  (TILE_O * A_STRIDE)               // |bf16(0.5*w)|   (8704)
#define SMEM_B   (2 * TILE_O * A_STRIDE)           // bf16(x)         (17408)
#define SMEM_TOTAL (SMEM_B + CIN * B_STRIDE)       // 35840

#define ABS2 0x7FFF7FFFu        // clears both bf16 sign bits

__device__ __forceinline__ uint32_t smem_u32(const void* p) {
    uint32_t a;
    asm("{ .reg .u64 t; cvta.to.shared.u64 t, %1; cvt.u32.u64 %0, t; }" : "=r"(a) : "l"(p));
    return a;
}
__device__ __forceinline__ uint32_t pack_bf16x2(float lo, float hi) {
    uint32_t r;
    asm("cvt.rn.bf16x2.f32 %0, %1, %2;" : "=r"(r) : "f"(hi), "f"(lo));
    return r;
}
__device__ __forceinline__ void sts64(uint32_t addr, uint32_t a, uint32_t b) {
    asm volatile("st.shared.v2.b32 [%0], {%1,%2};" :: "r"(addr), "r"(a), "r"(b) : "memory");
}
__device__ __forceinline__ void ldsm_x4(uint32_t addr, uint32_t* r) {
    asm volatile("ldmatrix.sync.aligned.m8n8.x4.shared.b16 {%0,%1,%2,%3}, [%4];"
                 : "=r"(r[0]), "=r"(r[1]), "=r"(r[2]), "=r"(r[3]) : "r"(addr));
}
__device__ __forceinline__ void ldsm_x4_trans(uint32_t addr, uint32_t* r) {
    asm volatile("ldmatrix.sync.aligned.m8n8.x4.trans.shared.b16 {%0,%1,%2,%3}, [%4];"
                 : "=r"(r[0]), "=r"(r[1]), "=r"(r[2]), "=r"(r[3]) : "r"(addr));
}
__device__ __forceinline__ void mma_16816(float* c, const uint32_t* a, const uint32_t* b) {
    asm volatile(
        "mma.sync.aligned.m16n8k16.row.col.f32.bf16.bf16.f32 "
        "{%0,%1,%2,%3}, {%4,%5,%6,%7}, {%8,%9}, {%0,%1,%2,%3};"
        : "+f"(c[0]), "+f"(c[1]), "+f"(c[2]), "+f"(c[3])
        : "r"(a[0]), "r"(a[1]), "r"(a[2]), "r"(a[3]), "r"(b[0]), "r"(b[1]));
}

__global__ __launch_bounds__(THREADS, 5)
void pw_relu_mma_kernel(const float* __restrict__ x,
                        const float* __restrict__ w,
                        float* __restrict__ out) {
    extern __shared__ char smem[];
    const uint32_t sb = smem_u32(smem);
    const int tid  = threadIdx.x;
    const int lane = tid & 31;
    const int wid  = tid >> 5;
    const int b  = blockIdx.z;
    const int o0 = blockIdx.y * TILE_O;
    const int p0 = blockIdx.x * TILE_P;

    // ---- staging maps ----
    const int pf = tid & 15;               // p = 4*pf
    const int i0 = tid >> 4;               // 0..7 (X row base)
    const float* xb = x + (size_t)b * CIN * HW + p0 + pf * 4;
    const int iv = tid & 31;               // i = 4*iv
    const int oo = tid >> 5;               // 0..3 (W row base)
    const float* wb = w + (size_t)(o0 + oo) * CIN + iv * 4;

    // ---- front-load batch 0: W (8 f4) + X rows i0+16it (8 f4) ----
    float4 wv[8], xv[8];
#pragma unroll
    for (int it = 0; it < 8; it++)
        wv[it] = *(const float4*)(wb + (size_t)(it * 4) * CIN);      // rows o = oo+4it
#pragma unroll
    for (int it = 0; it < 8; it++)
        xv[it] = *(const float4*)(xb + (size_t)(i0 + it * 16) * HW);

    // ---- stage W: Wh = bf16(0.5*w), Wa = |Wh|  (pre-scale folds the final /2,
    //      pre-abs removes 4 ANDs/iter from the mainloop) ----
#pragma unroll
    for (int it = 0; it < 8; it++) {
        const int o = oo + it * 4;
        float4 v = wv[it];
        uint32_t h0 = pack_bf16x2(0.5f * v.x, 0.5f * v.y);
        uint32_t h1 = pack_bf16x2(0.5f * v.z, 0.5f * v.w);
        sts64(sb + SMEM_AH + (uint32_t)o * A_STRIDE + iv * 8, h0, h1);
        sts64(sb + SMEM_AA + (uint32_t)o * A_STRIDE + iv * 8, h0 & ABS2, h1 & ABS2);
    }
    // ---- stage X plain bf16 [k=i][p], batch 0 ----
#pragma unroll
    for (int it = 0; it < 8; it++) {
        const int i = i0 + it * 16;
        float4 v = xv[it];
        sts64(sb + SMEM_B + (uint32_t)i * B_STRIDE + pf * 8,
              pack_bf16x2(v.x, v.y), pack_bf16x2(v.z, v.w));
    }
    // ---- batch 1: X rows i0+8+16it ----
#pragma unroll
    for (int it = 0; it < 8; it++)
        xv[it] = *(const float4*)(xb + (size_t)(i0 + 8 + it * 16) * HW);
#pragma unroll
    for (int it = 0; it < 8; it++) {
        const int i = i0 + 8 + it * 16;
        float4 v = xv[it];
        sts64(sb + SMEM_B + (uint32_t)i * B_STRIDE + pf * 8,
              pack_bf16x2(v.x, v.y), pack_bf16x2(v.z, v.w));
    }
    __syncthreads();

    // ---- mainloop: warp grid 2(m) x 2(n), warp tile 16(o) x 32(p), 8 k16-iters
    //      acc += Wh·X + Wa·|X|  ==  Σ relu(w·x) / ... (scale already in Wh) ----
    const int warp_m = wid & 1;
    const int warp_n = wid >> 1;
    const uint32_t aAddrH = sb + SMEM_AH + (uint32_t)(warp_m * 16 + (lane & 15)) * A_STRIDE
                            + (uint32_t)(lane >> 4) * 16;
    const uint32_t aAddrA = aAddrH + (SMEM_AA - SMEM_AH);
    const uint32_t bAddr0 = sb + SMEM_B + (uint32_t)(lane & 15) * B_STRIDE
                            + (uint32_t)(warp_n * 64) + (uint32_t)(lane >> 4) * 16;

    float acc[4][4];
#pragma unroll
    for (int ns = 0; ns < 4; ns++)
#pragma unroll
        for (int j = 0; j < 4; j++) acc[ns][j] = 0.f;

#pragma unroll
    for (int kk = 0; kk < CIN / 16; kk++) {
        uint32_t ah[4], aa[4], bx[2][4];
        ldsm_x4(aAddrH + kk * 32, ah);
        ldsm_x4(aAddrA + kk * 32, aa);
        ldsm_x4_trans(bAddr0 + (uint32_t)kk * (16 * B_STRIDE), bx[0]);
        ldsm_x4_trans(bAddr0 + (uint32_t)kk * (16 * B_STRIDE) + 32, bx[1]);
        uint32_t xa[2][4];
#pragma unroll
        for (int g = 0; g < 2; g++)
#pragma unroll
            for (int j = 0; j < 4; j++) xa[g][j] = bx[g][j] & ABS2;
        mma_16816(acc[0], ah, &bx[0][0]);
        mma_16816(acc[1], ah, &bx[0][2]);
        mma_16816(acc[2], ah, &bx[1][0]);
        mma_16816(acc[3], ah, &bx[1][2]);
        mma_16816(acc[0], aa, &xa[0][0]);
        mma_16816(acc[1], aa, &xa[0][2]);
        mma_16816(acc[2], aa, &xa[1][0]);
        mma_16816(acc[3], aa, &xa[1][2]);
    }

    // ---- epilogue: pure coalesced float2 stores (scale folded into Wh) ----
    const int r  = lane >> 2;
    const int c2 = (lane & 3) * 2;
    float* ob = out + ((size_t)b * COUT + o0 + warp_m * 16) * HW + p0 + warp_n * 32 + c2;
#pragma unroll
    for (int ns = 0; ns < 4; ns++) {
        *(float2*)(ob + (size_t)r * HW + ns * 8)       = make_float2(acc[ns][0], acc[ns][1]);
        *(float2*)(ob + (size_t)(r + 8) * HW + ns * 8) = make_float2(acc[ns][2], acc[ns][3]);
    }
}

extern "C" void kernel_launch(void* const* d_in, const int* in_sizes, int n_in,
                              void* d_out, int out_size) {
    const float* x = (const float*)d_in[0];   // (4,128,32,32)
    const float* w = (const float*)d_in[1];   // (256*128,1,1,1)
    float* out = (float*)d_out;               // (4,256,32,32)
    dim3 grid(HW / TILE_P, COUT / TILE_O, BATCH);   // (16, 8, 4) = 512 CTAs
    pw_relu_mma_kernel<<<grid, THREADS, SMEM_TOTAL>>>(x, w, out);
}

// round 12
// speedup vs baseline: 1.0511x; 1.0511x over previous
#include <cuda_runtime.h>
#include <cuda_bf16.h>
#include <cstdint>

#define BATCH 4
#define CIN   128
#define COUT  256
#define HW    1024
#define TILE_O 32
#define TILE_P 64
#define THREADS 128
#define KC     64            // k-chunk

// smem (bytes): strides are 16B multiples with (stride/4 mod 32)==4 -> ldmatrix
// row addresses walk 4 banks per row, conflict-free per 8-row phase.
#define A_STRIDE 272         // 128 halves + 8 pad
#define B_STRIDE 144         // 64 halves + 8 pad
#define SMEM_A   0
#define SMEM_B0  (TILE_O * A_STRIDE)               // 8704
#define SMEM_B1  (SMEM_B0 + KC * B_STRIDE)         // 17920
#define SMEM_TOTAL (SMEM_B1 + KC * B_STRIDE)       // 27136 (<48KB)

#define ABS2 0x7FFF7FFFu     // clears both bf16 sign bits

__device__ __forceinline__ uint32_t smem_u32(const void* p) {
    uint32_t a;
    asm("{ .reg .u64 t; cvta.to.shared.u64 t, %1; cvt.u32.u64 %0, t; }" : "=r"(a) : "l"(p));
    return a;
}
__device__ __forceinline__ uint32_t pack_bf16x2(float lo, float hi) {
    uint32_t r;
    asm("cvt.rn.bf16x2.f32 %0, %1, %2;" : "=r"(r) : "f"(hi), "f"(lo));
    return r;
}
__device__ __forceinline__ void sts64(uint32_t addr, uint32_t a, uint32_t b) {
    asm volatile("st.shared.v2.b32 [%0], {%1,%2};" :: "r"(addr), "r"(a), "r"(b) : "memory");
}
__device__ __forceinline__ void ldsm_x4(uint32_t addr, uint32_t* r) {
    asm volatile("ldmatrix.sync.aligned.m8n8.x4.shared.b16 {%0,%1,%2,%3}, [%4];"
                 : "=r"(r[0]), "=r"(r[1]), "=r"(r[2]), "=r"(r[3]) : "r"(addr));
}
__device__ __forceinline__ void ldsm_x4_trans(uint32_t addr, uint32_t* r) {
    asm volatile("ldmatrix.sync.aligned.m8n8.x4.trans.shared.b16 {%0,%1,%2,%3}, [%4];"
                 : "=r"(r[0]), "=r"(r[1]), "=r"(r[2]), "=r"(r[3]) : "r"(addr));
}
__device__ __forceinline__ void mma_16816(float* c, const uint32_t* a, const uint32_t* b) {
    asm volatile(
        "mma.sync.aligned.m16n8k16.row.col.f32.bf16.bf16.f32 "
        "{%0,%1,%2,%3}, {%4,%5,%6,%7}, {%8,%9}, {%0,%1,%2,%3};"
        : "+f"(c[0]), "+f"(c[1]), "+f"(c[2]), "+f"(c[3])
        : "r"(a[0]), "r"(a[1]), "r"(a[2]), "r"(a[3]), "r"(b[0]), "r"(b[1]));
}

// One k16 step of the abs-trick mainloop: accS += W·X, accA += |W|·|X|.
__device__ __forceinline__ void k_step(uint32_t aAddr, uint32_t bAddr,
                                       float accS[4][4], float accA[4][4]) {
    uint32_t aw[4], bx[2][4];
    ldsm_x4(aAddr, aw);
    ldsm_x4_trans(bAddr, bx[0]);
    ldsm_x4_trans(bAddr + 32, bx[1]);
    uint32_t wa[4], xa[2][4];
#pragma unroll
    for (int j = 0; j < 4; j++) wa[j] = aw[j] & ABS2;
#pragma unroll
    for (int g = 0; g < 2; g++)
#pragma unroll
        for (int j = 0; j < 4; j++) xa[g][j] = bx[g][j] & ABS2;
    mma_16816(accS[0], aw, &bx[0][0]);
    mma_16816(accA[0], wa, &xa[0][0]);
    mma_16816(accS[1], aw, &bx[0][2]);
    mma_16816(accA[1], wa, &xa[0][2]);
    mma_16816(accS[2], aw, &bx[1][0]);
    mma_16816(accA[2], wa, &xa[1][0]);
    mma_16816(accS[3], aw, &bx[1][2]);
    mma_16816(accA[3], wa, &xa[1][2]);
}

__global__ __launch_bounds__(THREADS, 4)
void pw_relu_mma_kernel(const float* __restrict__ x,
                        const float* __restrict__ w,
                        float* __restrict__ out) {
    extern __shared__ char smem[];
    const uint32_t sb = smem_u32(smem);
    const int tid  = threadIdx.x;
    const int lane = tid & 31;
    const int wid  = tid >> 5;
    const int b  = blockIdx.z;
    const int o0 = blockIdx.y * TILE_O;
    const int p0 = blockIdx.x * TILE_P;

    // ---- staging maps ----
    const int pf = tid & 15;               // p = 4*pf
    const int i0 = tid >> 4;               // 0..7 (X row base within a chunk)
    const float* xb = x + (size_t)b * CIN * HW + p0 + pf * 4;
    const int iv = tid & 31;               // i = 4*iv
    const int oo = tid >> 5;               // 0..3 (W row base)
    const float* wb = w + (size_t)(o0 + oo) * CIN + iv * 4;

    // ---- front-load W (8 f4) + X chunk0 rows 0..63 (8 f4) ----
    float4 wv[8], xv[8];
#pragma unroll
    for (int it = 0; it < 8; it++)
        wv[it] = *(const float4*)(wb + (size_t)(it * 4) * CIN);      // rows o = oo+4it
#pragma unroll
    for (int it = 0; it < 8; it++)
        xv[it] = *(const float4*)(xb + (size_t)(i0 + it * 8) * HW);  // i = i0+8it < 64

    // ---- stage W plain bf16 [o][k] ----
#pragma unroll
    for (int it = 0; it < 8; it++) {
        const int o = oo + it * 4;
        float4 v = wv[it];
        sts64(sb + SMEM_A + (uint32_t)o * A_STRIDE + iv * 8,
              pack_bf16x2(v.x, v.y), pack_bf16x2(v.z, v.w));
    }
    // ---- stage X chunk0 ----
#pragma unroll
    for (int it = 0; it < 8; it++) {
        const int i = i0 + it * 8;
        float4 v = xv[it];
        sts64(sb + SMEM_B0 + (uint32_t)i * B_STRIDE + pf * 8,
              pack_bf16x2(v.x, v.y), pack_bf16x2(v.z, v.w));
    }
    __syncthreads();

    // ---- per-warp fragment bases ----
    const int warp_m = wid & 1;
    const int warp_n = wid >> 1;
    const uint32_t aAddr0 = sb + SMEM_A + (uint32_t)(warp_m * 16 + (lane & 15)) * A_STRIDE
                            + (uint32_t)(lane >> 4) * 16;
    const uint32_t bFrag  = (uint32_t)(lane & 15) * B_STRIDE
                            + (uint32_t)(warp_n * 64) + (uint32_t)(lane >> 4) * 16;

    float accS[4][4], accA[4][4];
#pragma unroll
    for (int ns = 0; ns < 4; ns++)
#pragma unroll
        for (int j = 0; j < 4; j++) { accS[ns][j] = 0.f; accA[ns][j] = 0.f; }

    // ---- chunk 0 mainloop, with X chunk1 LDGs interleaved (latency hidden) ----
    float4 yv0[4], yv1[4];
#pragma unroll
    for (int it = 0; it < 4; it++)      // rows 64..95
        yv0[it] = *(const float4*)(xb + (size_t)(64 + i0 + it * 8) * HW);
    k_step(aAddr0 + 0 * 32, sb + SMEM_B0 + bFrag + 0 * (16 * B_STRIDE), accS, accA);
    k_step(aAddr0 + 1 * 32, sb + SMEM_B0 + bFrag + 1 * (16 * B_STRIDE), accS, accA);
#pragma unroll
    for (int it = 0; it < 4; it++)      // rows 96..127
        yv1[it] = *(const float4*)(xb + (size_t)(96 + i0 + it * 8) * HW);
    k_step(aAddr0 + 2 * 32, sb + SMEM_B0 + bFrag + 2 * (16 * B_STRIDE), accS, accA);
    k_step(aAddr0 + 3 * 32, sb + SMEM_B0 + bFrag + 3 * (16 * B_STRIDE), accS, accA);

    // ---- stage X chunk1 ----
#pragma unroll
    for (int it = 0; it < 4; it++) {
        const int i = i0 + it * 8;              // local row in B1
        float4 v = yv0[it];
        sts64(sb + SMEM_B1 + (uint32_t)i * B_STRIDE + pf * 8,
              pack_bf16x2(v.x, v.y), pack_bf16x2(v.z, v.w));
    }
#pragma unroll
    for (int it = 0; it < 4; it++) {
        const int i = 32 + i0 + it * 8;
        float4 v = yv1[it];
        sts64(sb + SMEM_B1 + (uint32_t)i * B_STRIDE + pf * 8,
              pack_bf16x2(v.x, v.y), pack_bf16x2(v.z, v.w));
    }
    __syncthreads();

    // ---- chunk 1 mainloop ----
#pragma unroll
    for (int kk = 0; kk < 4; kk++)
        k_step(aAddr0 + (4 + kk) * 32, sb + SMEM_B1 + bFrag + (uint32_t)kk * (16 * B_STRIDE),
               accS, accA);

    // ---- epilogue: out = 0.5*(S + A), coalesced float2 stores ----
    const int r  = lane >> 2;
    const int c2 = (lane & 3) * 2;
    float* ob = out + ((size_t)b * COUT + o0 + warp_m * 16) * HW + p0 + warp_n * 32 + c2;
#pragma unroll
    for (int ns = 0; ns < 4; ns++) {
        float v0 = (accS[ns][0] + accA[ns][0]) * 0.5f;
        float v1 = (accS[ns][1] + accA[ns][1]) * 0.5f;
        float v2 = (accS[ns][2] + accA[ns][2]) * 0.5f;
        float v3 = (accS[ns][3] + accA[ns][3]) * 0.5f;
        *(float2*)(ob + (size_t)r * HW + ns * 8)       = make_float2(v0, v1);
        *(float2*)(ob + (size_t)(r + 8) * HW + ns * 8) = make_float2(v2, v3);
    }
}

extern "C" void kernel_launch(void* const* d_in, const int* in_sizes, int n_in,
                              void* d_out, int out_size) {
    const float* x = (const float*)d_in[0];   // (4,128,32,32)
    const float* w = (const float*)d_in[1];   // (256*128,1,1,1)
    float* out = (float*)d_out;               // (4,256,32,32)
    dim3 grid(HW / TILE_P, COUT / TILE_O, BATCH);   // (16, 8, 4) = 512 CTAs
    pw_relu_mma_kernel<<<grid, THREADS, SMEM_TOTAL>>>(x, w, out);
}

// round 14
// speedup vs baseline: 1.0992x; 1.0458x over previous
#include <cuda_runtime.h>
#include <cuda_bf16.h>
#include <cstdint>

#define BATCH 4
#define CIN   128
#define COUT  256
#define HW    1024
#define TILE_O 32
#define TILE_P 64
#define THREADS 256

// smem (bytes): strides are 16B multiples with (stride/4 mod 32)==4 -> ldmatrix
// row addresses walk 4 banks per row, conflict-free per 8-row phase.
#define A_STRIDE 272            // 128 halves + 8 pad
#define B_STRIDE 144            // 64 halves + 8 pad
#define SMEM_A   0
#define SMEM_B   (TILE_O * A_STRIDE)              // 8704
#define SMEM_TOTAL (SMEM_B + CIN * B_STRIDE)      // 27136 (<48KB)

#define ABS2 0x7FFF7FFFu        // clears both bf16 sign bits

__device__ __forceinline__ uint32_t smem_u32(const void* p) {
    uint32_t a;
    asm("{ .reg .u64 t; cvta.to.shared.u64 t, %1; cvt.u32.u64 %0, t; }" : "=r"(a) : "l"(p));
    return a;
}
__device__ __forceinline__ uint32_t pack_bf16x2(float lo, float hi) {
    uint32_t r;
    asm("cvt.rn.bf16x2.f32 %0, %1, %2;" : "=r"(r) : "f"(hi), "f"(lo));
    return r;
}
__device__ __forceinline__ void sts64(uint32_t addr, uint32_t a, uint32_t b) {
    asm volatile("st.shared.v2.b32 [%0], {%1,%2};" :: "r"(addr), "r"(a), "r"(b) : "memory");
}
__device__ __forceinline__ void ldsm_x4(uint32_t addr, uint32_t* r) {
    asm volatile("ldmatrix.sync.aligned.m8n8.x4.shared.b16 {%0,%1,%2,%3}, [%4];"
                 : "=r"(r[0]), "=r"(r[1]), "=r"(r[2]), "=r"(r[3]) : "r"(addr));
}
__device__ __forceinline__ void ldsm_x4_trans(uint32_t addr, uint32_t* r) {
    asm volatile("ldmatrix.sync.aligned.m8n8.x4.trans.shared.b16 {%0,%1,%2,%3}, [%4];"
                 : "=r"(r[0]), "=r"(r[1]), "=r"(r[2]), "=r"(r[3]) : "r"(addr));
}
__device__ __forceinline__ void mma_16816(float* c, const uint32_t* a, const uint32_t* b) {
    asm volatile(
        "mma.sync.aligned.m16n8k16.row.col.f32.bf16.bf16.f32 "
        "{%0,%1,%2,%3}, {%4,%5,%6,%7}, {%8,%9}, {%0,%1,%2,%3};"
        : "+f"(c[0]), "+f"(c[1]), "+f"(c[2]), "+f"(c[3])
        : "r"(a[0]), "r"(a[1]), "r"(a[2]), "r"(a[3]), "r"(b[0]), "r"(b[1]));
}

__global__ __launch_bounds__(THREADS, 3)
void pw_relu_mma_kernel(const float* __restrict__ x,
                        const float* __restrict__ w,
                        float* __restrict__ out) {
    extern __shared__ char smem[];
    const uint32_t sb = smem_u32(smem);
    const int tid  = threadIdx.x;
    const int lane = tid & 31;
    const int wid  = tid >> 5;             // 0..7
    const int b  = blockIdx.z;
    const int o0 = blockIdx.y * TILE_O;
    const int p0 = blockIdx.x * TILE_P;

    // ---- staging maps (256 threads) ----
    const int pf = tid & 15;               // p = 4*pf
    const int i0 = tid >> 4;               // 0..15 (X row base)
    const float* xb = x + (size_t)b * CIN * HW + p0 + pf * 4;
    const int iv = tid & 31;               // i = 4*iv
    const int oo = tid >> 5;               // 0..7 (W row base)
    const float* wb = w + (size_t)(o0 + oo) * CIN + iv * 4;

    // ---- front-load: X (8 f4, rows i0+16it) + W (4 f4, rows oo+8it) ----
    float4 xv[8], wv[4];
#pragma unroll
    for (int it = 0; it < 8; it++)
        xv[it] = *(const float4*)(xb + (size_t)(i0 + it * 16) * HW);
#pragma unroll
    for (int it = 0; it < 4; it++)
        wv[it] = *(const float4*)(wb + (size_t)(it * 8) * CIN);

    // ---- stage W plain bf16 [o][k] ----
#pragma unroll
    for (int it = 0; it < 4; it++) {
        const int o = oo + it * 8;
        float4 v = wv[it];
        sts64(sb + SMEM_A + (uint32_t)o * A_STRIDE + iv * 8,
              pack_bf16x2(v.x, v.y), pack_bf16x2(v.z, v.w));
    }
    // ---- stage X plain bf16 [k=i][p] ----
#pragma unroll
    for (int it = 0; it < 8; it++) {
        const int i = i0 + it * 16;
        float4 v = xv[it];
        sts64(sb + SMEM_B + (uint32_t)i * B_STRIDE + pf * 8,
              pack_bf16x2(v.x, v.y), pack_bf16x2(v.z, v.w));
    }
    __syncthreads();

    // ---- mainloop: warp grid 2(m) x 4(n), warp tile 16(o) x 16(p), 8 k16-iters
    //      accS += W·X ; accA += |W|·|X| ; out = (S+A)/2 ----
    const int warp_m = wid & 1;            // 2 -> 32 o
    const int warp_n = wid >> 1;           // 4 -> 64 p
    const uint32_t aAddr0 = sb + SMEM_A + (uint32_t)(warp_m * 16 + (lane & 15)) * A_STRIDE
                            + (uint32_t)(lane >> 4) * 16;
    const uint32_t bAddr0 = sb + SMEM_B + (uint32_t)(lane & 15) * B_STRIDE
                            + (uint32_t)(warp_n * 32) + (uint32_t)(lane >> 4) * 16;

    float accS[2][4], accA[2][4];
#pragma unroll
    for (int ns = 0; ns < 2; ns++)
#pragma unroll
        for (int j = 0; j < 4; j++) { accS[ns][j] = 0.f; accA[ns][j] = 0.f; }

#pragma unroll
    for (int kk = 0; kk < CIN / 16; kk++) {
        uint32_t aw[4], bx[4];
        ldsm_x4(aAddr0 + kk * 32, aw);
        ldsm_x4_trans(bAddr0 + (uint32_t)kk * (16 * B_STRIDE), bx);
        uint32_t wa[4], xa[4];
#pragma unroll
        for (int j = 0; j < 4; j++) { wa[j] = aw[j] & ABS2; xa[j] = bx[j] & ABS2; }
        mma_16816(accS[0], aw, &bx[0]);
        mma_16816(accA[0], wa, &xa[0]);
        mma_16816(accS[1], aw, &bx[2]);
        mma_16816(accA[1], wa, &xa[2]);
    }

    // ---- epilogue: out = 0.5*(S + A), coalesced float2 stores ----
    const int r  = lane >> 2;
    const int c2 = (lane & 3) * 2;
    float* ob = out + ((size_t)b * COUT + o0 + warp_m * 16) * HW + p0 + warp_n * 16 + c2;
#pragma unroll
    for (int ns = 0; ns < 2; ns++) {
        float v0 = (accS[ns][0] + accA[ns][0]) * 0.5f;
        float v1 = (accS[ns][1] + accA[ns][1]) * 0.5f;
        float v2 = (accS[ns][2] + accA[ns][2]) * 0.5f;
        float v3 = (accS[ns][3] + accA[ns][3]) * 0.5f;
        *(float2*)(ob + (size_t)r * HW + ns * 8)       = make_float2(v0, v1);
        *(float2*)(ob + (size_t)(r + 8) * HW + ns * 8) = make_float2(v2, v3);
    }
}

extern "C" void kernel_launch(void* const* d_in, const int* in_sizes, int n_in,
                              void* d_out, int out_size) {
    const float* x = (const float*)d_in[0];   // (4,128,32,32)
    const float* w = (const float*)d_in[1];   // (256*128,1,1,1)
    float* out = (float*)d_out;               // (4,256,32,32)
    dim3 grid(HW / TILE_P, COUT / TILE_O, BATCH);   // (16, 8, 4) = 512 CTAs
    pw_relu_mma_kernel<<<grid, THREADS, SMEM_TOTAL>>>(x, w, out);
}